// round 16
// baseline (speedup 1.0000x reference)
#include <cuda_runtime.h>
#include <cuda_fp16.h>
#include <cstdint>
#include <math.h>

// ---------------- problem constants ----------------
#define BDIM 2
#define NQ   4096
#define NK   4096
#define AQ   128
#define AM   64
#define H    4
#define DK   32
#define DV   16
#define ODIM 64
#define QSCALE (0.17677669529663687f * 1.4426950408889634f)  // scale * log2(e)

// proj grid layout
#define NQBLK (BDIM*NQ/64)     // 128 Q-proj blocks
#define NKBLK (BDIM*NK/32)     // 256 KV-proj blocks

// attn smem stage: K[128][80B] | V[128][48B]; 3 stages
#define OFF_V 10240
#define STG   16384
#define SMEM_SZ (3*STG)

typedef unsigned long long u64;

// ---------------- scratch ----------------
__device__ __align__(16) unsigned short g_Q[(size_t)BDIM*H*NQ*DK]; // fp16, prescaled
__device__ __align__(16) unsigned short g_K[(size_t)BDIM*H*NK*32]; // [bh][pos][32] fp16
__device__ __align__(16) unsigned short g_V[(size_t)BDIM*H*NK*16]; // [bh][pos][16] fp16
__device__ int g_cnt[BDIM];

// ---------------- helpers ----------------
__device__ __forceinline__ uint32_t smem_u32(const void* p) {
    uint32_t a;
    asm("{ .reg .u64 t; cvta.to.shared.u64 t, %1; cvt.u32.u64 %0, t; }" : "=r"(a) : "l"(p));
    return a;
}
__device__ __forceinline__ float ex2f(float x) {
    float y; asm("ex2.approx.f32 %0, %1;" : "=f"(y) : "f"(x)); return y;
}
__device__ __forceinline__ float rcpf(float x) {
    float y; asm("rcp.approx.f32 %0, %1;" : "=f"(y) : "f"(x)); return y;
}
__device__ __forceinline__ uint32_t ex2h2(uint32_t x) {
    uint32_t y; asm("ex2.approx.f16x2 %0, %1;" : "=r"(y) : "r"(x)); return y;
}
__device__ __forceinline__ uint32_t pkf2h(float a, float b) {
    __half2 t = __floats2half2_rn(a, b);
    return *reinterpret_cast<uint32_t*>(&t);
}
__device__ __forceinline__ u64 ffma2(u64 a, u64 b, u64 c) {
    u64 d; asm("fma.rn.f32x2 %0, %1, %2, %3;" : "=l"(d) : "l"(a), "l"(b), "l"(c)); return d;
}
__device__ __forceinline__ u64 pack2(float x, float y) {
    u64 d; asm("mov.b64 %0, {%1,%2};" : "=l"(d) : "f"(x), "f"(y)); return d;
}
__device__ __forceinline__ void unpack2(float& x, float& y, u64 v) {
    asm("mov.b64 {%0,%1}, %2;" : "=f"(x), "=f"(y) : "l"(v));
}
__device__ __forceinline__ unsigned short h16(float x) {
    __half h = __float2half(x);
    return *reinterpret_cast<unsigned short*>(&h);
}
__device__ __forceinline__ void mma16816h(float c[4], const uint32_t a[4], const uint32_t b[2]) {
    asm volatile("mma.sync.aligned.m16n8k16.row.col.f32.f16.f16.f32 "
        "{%0,%1,%2,%3}, {%4,%5,%6,%7}, {%8,%9}, {%0,%1,%2,%3};"
        : "+f"(c[0]), "+f"(c[1]), "+f"(c[2]), "+f"(c[3])
        : "r"(a[0]), "r"(a[1]), "r"(a[2]), "r"(a[3]), "r"(b[0]), "r"(b[1]));
}
__device__ __forceinline__ void ldmx4(uint32_t& v0, uint32_t& v1, uint32_t& v2, uint32_t& v3,
                                      uint32_t addr) {
    asm volatile("ldmatrix.sync.aligned.m8n8.x4.shared.b16 {%0,%1,%2,%3}, [%4];"
        : "=r"(v0), "=r"(v1), "=r"(v2), "=r"(v3) : "r"(addr));
}
__device__ __forceinline__ void ldmx4t(uint32_t& v0, uint32_t& v1, uint32_t& v2, uint32_t& v3,
                                       uint32_t addr) {
    asm volatile("ldmatrix.sync.aligned.m8n8.x4.trans.shared.b16 {%0,%1,%2,%3}, [%4];"
        : "=r"(v0), "=r"(v1), "=r"(v2), "=r"(v3) : "r"(addr));
}
__device__ __forceinline__ void cpa16(uint32_t dst, const void* src) {
    asm volatile("cp.async.cg.shared.global [%0], [%1], 16;" :: "r"(dst), "l"(src));
}
#define CPA_COMMIT() asm volatile("cp.async.commit_group;" ::: "memory")
#define CPA_WAIT(n)  asm volatile("cp.async.wait_group %0;" :: "n"(n) : "memory")

// ================= fused projection kernel (unchanged from R15) =================
__global__ __launch_bounds__(256) void proj_kernel(
    const int* __restrict__ mask,
    const float* __restrict__ qd, const float* __restrict__ qw,
    const float* __restrict__ md, const float* __restrict__ kw,
    const float* __restrict__ vw,
    const float* __restrict__ ob, float* __restrict__ out) {
    __shared__ float rowT[AQ][66];
    __shared__ int wsum[8];
    __shared__ int s_val;
    __shared__ int pos_s[32];
    int t = threadIdx.x;
    int lane = t & 31, wid = t >> 5;

    if (blockIdx.x < 2) {
        int b = blockIdx.x;
        const int4* mb4 = (const int4*)(mask + (size_t)b*NK);
        int c = 0;
        for (int i = t; i < NK/4; i += 256) {
            int4 v = mb4[i];
            c += (v.x != 0) + (v.y != 0) + (v.z != 0) + (v.w != 0);
        }
        #pragma unroll
        for (int d = 16; d > 0; d >>= 1) c += __shfl_xor_sync(0xffffffffu, c, d);
        if (lane == 0) wsum[wid] = c;
        __syncthreads();
        if (t == 0) {
            int s = 0;
            #pragma unroll
            for (int i = 0; i < 8; i++) s += wsum[i];
            g_cnt[b] = s; s_val = s;
        }
        __syncthreads();
        int cnt = s_val;
        int pad = ((cnt + 127) & ~127) - cnt;
        uint4 z = make_uint4(0,0,0,0);
        for (int i = t; i < pad*4*4; i += 256) {
            int h = i / (pad*4), r = i % (pad*4);
            ((uint4*)(g_K + ((size_t)(b*H + h)*NK + cnt + (r >> 2))*32))[r & 3] = z;
        }
        for (int i = t; i < pad*4*2; i += 256) {
            int h = i / (pad*2), r = i % (pad*2);
            ((uint4*)(g_V + ((size_t)(b*H + h)*NK + cnt + (r >> 1))*16))[r & 1] = z;
        }
    } else if (blockIdx.x < 2 + NQBLK) {
        int bq0 = (int)(blockIdx.x - 2)*64;
        int b = bq0 >> 12;
        for (int i = t; i < 64*AQ; i += 256) {
            int r = i >> 7, a = i & 127;
            rowT[a][r] = qd[(size_t)(bq0 + r)*AQ + a];
        }
        __syncthreads();

        int rbase = wid*8;
        int c0 = lane*4;
        u64 acc[4][4];
        #pragma unroll
        for (int ci = 0; ci < 4; ci++)
            #pragma unroll
            for (int rp = 0; rp < 4; rp++) acc[ci][rp] = 0ull;

        for (int a = 0; a < AQ; a++) {
            float4 w4 = *(const float4*)(qw + a*(H*DK) + c0);
            u64 r0 = *(const u64*)&rowT[a][rbase];
            u64 r1 = *(const u64*)&rowT[a][rbase+2];
            u64 r2 = *(const u64*)&rowT[a][rbase+4];
            u64 r3 = *(const u64*)&rowT[a][rbase+6];
            u64 wx = pack2(w4.x, w4.x), wy = pack2(w4.y, w4.y);
            u64 wz = pack2(w4.z, w4.z), ww = pack2(w4.w, w4.w);
            acc[0][0] = ffma2(r0, wx, acc[0][0]); acc[0][1] = ffma2(r1, wx, acc[0][1]);
            acc[0][2] = ffma2(r2, wx, acc[0][2]); acc[0][3] = ffma2(r3, wx, acc[0][3]);
            acc[1][0] = ffma2(r0, wy, acc[1][0]); acc[1][1] = ffma2(r1, wy, acc[1][1]);
            acc[1][2] = ffma2(r2, wy, acc[1][2]); acc[1][3] = ffma2(r3, wy, acc[1][3]);
            acc[2][0] = ffma2(r0, wz, acc[2][0]); acc[2][1] = ffma2(r1, wz, acc[2][1]);
            acc[2][2] = ffma2(r2, wz, acc[2][2]); acc[2][3] = ffma2(r3, wz, acc[2][3]);
            acc[3][0] = ffma2(r0, ww, acc[3][0]); acc[3][1] = ffma2(r1, ww, acc[3][1]);
            acc[3][2] = ffma2(r2, ww, acc[3][2]); acc[3][3] = ffma2(r3, ww, acc[3][3]);
        }

        int h = c0 >> 5, cc = c0 & 31;
        unsigned short* qb = g_Q + ((size_t)(b*H + h)*NQ + (bq0 & (NQ-1))) * DK + cc;
        #pragma unroll
        for (int rp = 0; rp < 4; rp++) {
            float f[4][2];
            #pragma unroll
            for (int ci = 0; ci < 4; ci++) unpack2(f[ci][0], f[ci][1], acc[ci][rp]);
            #pragma unroll
            for (int e = 0; e < 2; e++) {
                int r = rbase + 2*rp + e;
                u64 pk = (u64)h16(f[0][e]*QSCALE)
                       | ((u64)h16(f[1][e]*QSCALE) << 16)
                       | ((u64)h16(f[2][e]*QSCALE) << 32)
                       | ((u64)h16(f[3][e]*QSCALE) << 48);
                *(u64*)(qb + (size_t)r*DK) = pk;
            }
        }
        const float4* b4 = (const float4*)ob;
        for (int i = t; i < 64*16; i += 256) {
            int r = i >> 4, c4 = i & 15;
            ((float4*)(out + (size_t)(bq0 + r)*ODIM))[c4] = b4[c4];
        }
    } else {
        int k0 = (int)(blockIdx.x - 2 - NQBLK)*32;
        int b = k0 >> 12;
        int k0l = k0 & (NK-1);
        const int* mb = mask + (size_t)b*NK;

        int c = 0;
        const int4* mb4 = (const int4*)mb;
        for (int i = t; i < (k0l >> 2); i += 256) {
            int4 v = mb4[i];
            c += (v.x != 0) + (v.y != 0) + (v.z != 0) + (v.w != 0);
        }
        for (int i = t; i < 32*AM; i += 256) {
            int r = i >> 6, a = i & 63;
            rowT[a][r] = md[(size_t)(k0 + r)*AM + a];
        }
        #pragma unroll
        for (int d = 16; d > 0; d >>= 1) c += __shfl_xor_sync(0xffffffffu, c, d);
        if (lane == 0) wsum[wid] = c;
        __syncthreads();
        if (t == 0) {
            int s = 0;
            #pragma unroll
            for (int i = 0; i < 8; i++) s += wsum[i];
            s_val = s;
        }
        __syncthreads();
        if (wid == 0) {
            int m = mb[k0l + lane];
            int incl = (m != 0);
            #pragma unroll
            for (int d = 1; d < 32; d <<= 1) {
                int n = __shfl_up_sync(0xffffffffu, incl, d);
                if (lane >= d) incl += n;
            }
            pos_s[lane] = (m != 0) ? (s_val + incl - 1) : -1;
        }
        __syncthreads();

        if (wid < 4) {
            int rbase = wid*8, c0 = lane*4;
            u64 acc[4][4];
            #pragma unroll
            for (int ci = 0; ci < 4; ci++)
                #pragma unroll
                for (int rp = 0; rp < 4; rp++) acc[ci][rp] = 0ull;
            for (int a = 0; a < AM; a++) {
                float4 w4 = *(const float4*)(kw + a*(H*DK) + c0);
                u64 r0 = *(const u64*)&rowT[a][rbase];
                u64 r1 = *(const u64*)&rowT[a][rbase+2];
                u64 r2 = *(const u64*)&rowT[a][rbase+4];
                u64 r3 = *(const u64*)&rowT[a][rbase+6];
                u64 wx = pack2(w4.x, w4.x), wy = pack2(w4.y, w4.y);
                u64 wz = pack2(w4.z, w4.z), ww = pack2(w4.w, w4.w);
                acc[0][0] = ffma2(r0, wx, acc[0][0]); acc[0][1] = ffma2(r1, wx, acc[0][1]);
                acc[0][2] = ffma2(r2, wx, acc[0][2]); acc[0][3] = ffma2(r3, wx, acc[0][3]);
                acc[1][0] = ffma2(r0, wy, acc[1][0]); acc[1][1] = ffma2(r1, wy, acc[1][1]);
                acc[1][2] = ffma2(r2, wy, acc[1][2]); acc[1][3] = ffma2(r3, wy, acc[1][3]);
                acc[2][0] = ffma2(r0, wz, acc[2][0]); acc[2][1] = ffma2(r1, wz, acc[2][1]);
                acc[2][2] = ffma2(r2, wz, acc[2][2]); acc[2][3] = ffma2(r3, wz, acc[2][3]);
                acc[3][0] = ffma2(r0, ww, acc[3][0]); acc[3][1] = ffma2(r1, ww, acc[3][1]);
                acc[3][2] = ffma2(r2, ww, acc[3][2]); acc[3][3] = ffma2(r3, ww, acc[3][3]);
            }
            int h = c0 >> 5, cc = c0 & 31;
            unsigned short* kb = g_K + (size_t)(b*H + h)*NK*32 + cc;
            #pragma unroll
            for (int rp = 0; rp < 4; rp++) {
                float f[4][2];
                #pragma unroll
                for (int ci = 0; ci < 4; ci++) unpack2(f[ci][0], f[ci][1], acc[ci][rp]);
                #pragma unroll
                for (int e = 0; e < 2; e++) {
                    int pos = pos_s[rbase + 2*rp + e];
                    if (pos < 0) continue;
                    u64 pk = (u64)h16(f[0][e]) | ((u64)h16(f[1][e]) << 16)
                           | ((u64)h16(f[2][e]) << 32) | ((u64)h16(f[3][e]) << 48);
                    *(u64*)(kb + (size_t)pos*32) = pk;
                }
            }
        } else if (wid < 6) {
            int rbase = (wid - 4)*16, c0 = lane*2;
            u64 acc[2][8];
            #pragma unroll
            for (int ci = 0; ci < 2; ci++)
                #pragma unroll
                for (int rp = 0; rp < 8; rp++) acc[ci][rp] = 0ull;
            for (int a = 0; a < AM; a++) {
                float2 w2 = *(const float2*)(vw + a*(H*DV) + c0);
                u64 wx = pack2(w2.x, w2.x), wy = pack2(w2.y, w2.y);
                #pragma unroll
                for (int rp = 0; rp < 8; rp++) {
                    u64 rr = *(const u64*)&rowT[a][rbase + 2*rp];
                    acc[0][rp] = ffma2(rr, wx, acc[0][rp]);
                    acc[1][rp] = ffma2(rr, wy, acc[1][rp]);
                }
            }
            int h = c0 >> 4, cc = c0 & 15;
            unsigned short* vb = g_V + (size_t)(b*H + h)*NK*16 + cc;
            #pragma unroll
            for (int rp = 0; rp < 8; rp++) {
                float f0a, f0b, f1a, f1b;
                unpack2(f0a, f0b, acc[0][rp]);
                unpack2(f1a, f1b, acc[1][rp]);
                int p0 = pos_s[rbase + 2*rp], p1 = pos_s[rbase + 2*rp + 1];
                if (p0 >= 0) {
                    uint32_t pk = (uint32_t)h16(f0a) | ((uint32_t)h16(f1a) << 16);
                    *(uint32_t*)(vb + (size_t)p0*16) = pk;
                }
                if (p1 >= 0) {
                    uint32_t pk = (uint32_t)h16(f0b) | ((uint32_t)h16(f1b) << 16);
                    *(uint32_t*)(vb + (size_t)p1*16) = pk;
                }
            }
        }
    }
}

// ---------------- stage 2: attention, 8 warps (key-split), fused outproj ----------------
// grid = 512 blocks x 256 threads. Warps 0-3: keys [kb,kb+64); warps 4-7: [kb+64,kb+128).
// Warp pairs (qw, qw+4) own the same 16 q-rows; partials merged via smem at the end.
__device__ __forceinline__ void issue_tile(const unsigned char* Kg, const unsigned char* Vg,
                                           uint32_t stage, int tid) {
    #pragma unroll
    for (int i = 0; i < 2; i++) {                 // K tile 8KB: 512 x 16B over 256 thr
        int c = tid + (i << 8);
        int row = c >> 2, part = c & 3;
        cpa16(stage + (uint32_t)(row*80 + part*16), Kg + (size_t)c*16);
    }
    {                                             // V tile 4KB: 256 x 16B
        int row = tid >> 1, hf = tid & 1;
        cpa16(stage + OFF_V + (uint32_t)(row*48 + hf*16), Vg + (size_t)tid*16);
    }
}

__global__ __launch_bounds__(256) void attn_mma_kernel(
    const float* __restrict__ ow, float* __restrict__ out) {
    extern __shared__ __align__(16) unsigned char smem[];
    uint32_t sb = smem_u32(smem);
    int tid = threadIdx.x, warp = tid >> 5, lane = tid & 31;
    int qwarp = warp & 3, kwarp = warp >> 2;
    int g = lane >> 2, tg = lane & 3;
    int bid = blockIdx.x;
    int qt = bid & 63, bh = bid >> 6;
    int b = bh >> 2, h = bh & 3;
    int cnt = g_cnt[b];
    int ntiles = (cnt + 127) >> 7;

    uint32_t aQ[2][4];
    {
        const unsigned short* Qb = g_Q + (size_t)bh*NQ*DK;
        int r0 = qt*64 + qwarp*16 + g;
        #pragma unroll
        for (int s = 0; s < 2; s++)
            #pragma unroll
            for (int p = 0; p < 4; p++) {
                int row = r0 + (p & 1)*8;
                int col = tg*2 + s*16 + (p >> 1)*8;
                aQ[s][p] = *(const uint32_t*)(Qb + (size_t)row*DK + col);
            }
    }

    float o0[4] = {0.f,0.f,0.f,0.f}, o1[4] = {0.f,0.f,0.f,0.f};
    float oL[4] = {0.f,0.f,0.f,0.f};
    const uint32_t ones2 = 0x3C003C00u;
    uint32_t bOnes[2] = {ones2, ones2};

    const unsigned char* Kg = (const unsigned char*)g_K + (size_t)bh*NK*64;
    const unsigned char* Vg = (const unsigned char*)g_V + (size_t)bh*NK*32;

    int sel = lane >> 3;
    uint32_t kbase_lane = (uint32_t)((lane & 7)*80 + sel*16);

    issue_tile(Kg, Vg, sb, tid);
    CPA_COMMIT();

    int cur = 0;
    for (int t = 0; t < ntiles; t++) {
        int nxt = (cur == 2) ? 0 : cur + 1;
        if (t + 1 < ntiles) {
            issue_tile(Kg + (size_t)(t+1)*8192, Vg + (size_t)(t+1)*4096,
                       sb + (uint32_t)nxt*STG, tid);
            CPA_COMMIT();
            CPA_WAIT(1);
        } else {
            CPA_WAIT(0);
        }
        __syncthreads();

        uint32_t sK = sb + (uint32_t)cur*STG;
        uint32_t sV = sK + OFF_V;
        int kb2 = (t << 7) + kwarp*64;           // this warp's 64-key half
        bool full = (kb2 + 64) <= cnt;

        float sc[8][4];
        #pragma unroll
        for (int j = 0; j < 8; j++)
            sc[j][0] = sc[j][1] = sc[j][2] = sc[j][3] = 0.f;

        uint32_t kaddr = sK + kbase_lane + (uint32_t)(kwarp*5120);
        #pragma unroll
        for (int j = 0; j < 8; j++) {
            uint32_t v0, v1, v2, v3;
            ldmx4(v0, v1, v2, v3, kaddr);
            kaddr += 640;
            uint32_t k0r[2] = {v0, v1}, k1r[2] = {v2, v3};
            mma16816h(sc[j], aQ[0], k0r);
            mma16816h(sc[j], aQ[1], k1r);
        }

        uint32_t P[8][2];
        if (full) {
            #pragma unroll
            for (int j = 0; j < 8; j++) {
                P[j][0] = ex2h2(pkf2h(sc[j][0], sc[j][1]));
                P[j][1] = ex2h2(pkf2h(sc[j][2], sc[j][3]));
            }
        } else {
            #pragma unroll
            for (int j = 0; j < 8; j++) {
                float p[4];
                #pragma unroll
                for (int e = 0; e < 4; e++) {
                    float pv = ex2f(sc[j][e]);
                    int key = kb2 + j*8 + tg*2 + (e & 1);
                    p[e] = (key < cnt) ? pv : 0.f;
                }
                P[j][0] = pkf2h(p[0], p[1]);
                P[j][1] = pkf2h(p[2], p[3]);
            }
        }

        #pragma unroll
        for (int ks = 0; ks < 4; ks++) {
            uint32_t aP[4] = {P[2*ks][0], P[2*ks][1], P[2*ks+1][0], P[2*ks+1][1]};
            int part = lane >> 3;
            int key = kwarp*64 + ks*16 + ((part >> 1) << 3) + (lane & 7);
            uint32_t addr = sV + (uint32_t)(key*48 + (part & 1)*16);
            uint32_t v0, v1, v2, v3;
            ldmx4t(v0, v1, v2, v3, addr);
            uint32_t bA[2] = {v0, v2}, bB[2] = {v1, v3};
            mma16816h(o0, aP, bA);
            mma16816h(o1, aP, bB);
            mma16816h(oL, aP, bOnes);
        }
        cur = nxt;
    }

    // ---- merge key-halves across warp pairs via smem ----
    __syncthreads();
    float* comb = (float*)smem;                  // [4][32][12] = 6144 B
    float* was  = (float*)(smem + 8192);         // 16*66*4 = 4224 B
    if (kwarp == 1) {
        float* d = comb + (qwarp*32 + lane)*12;
        #pragma unroll
        for (int i = 0; i < 4; i++) { d[i] = o0[i]; d[4+i] = o1[i]; d[8+i] = oL[i]; }
    }
    __syncthreads();
    if (kwarp == 0) {
        const float* d = comb + (qwarp*32 + lane)*12;
        #pragma unroll
        for (int i = 0; i < 4; i++) { o0[i] += d[i]; o1[i] += d[4+i]; oL[i] += d[8+i]; }

        float inv0 = rcpf(oL[0]), inv1 = rcpf(oL[2]);
        int row0 = qwarp*16 + g;
        #pragma unroll
        for (int jn = 0; jn < 2; jn++) {
            const float* o = jn ? o1 : o0;
            int chan = jn*8 + tg*2;
            was[(chan+0)*66 + row0]     = o[0]*inv0;
            was[(chan+1)*66 + row0]     = o[1]*inv0;
            was[(chan+0)*66 + row0 + 8] = o[2]*inv1;
            was[(chan+1)*66 + row0 + 8] = o[3]*inv1;
        }
    }
    __syncthreads();

    // ---- fused output projection + RED.ADD (256 threads, 8 rows each) ----
    {
        int oc = tid & 63;
        int grp = tid >> 6;                      // 0..3 -> rows [grp*16, +16)
        float wreg[16];
        #pragma unroll
        for (int i = 0; i < 16; i++)
            wreg[i] = ow[(h*16 + i)*ODIM + oc];
        float* obase = out + ((size_t)b*NQ + qt*64)*ODIM + oc;
        #pragma unroll
        for (int qp = 0; qp < 8; qp++) {
            int q = grp*16 + qp*2;
            u64 acc = 0ull;
            #pragma unroll
            for (int i = 0; i < 16; i++)
                acc = ffma2(*(const u64*)&was[i*66 + q], pack2(wreg[i], wreg[i]), acc);
            float f0, f1; unpack2(f0, f1, acc);
            atomicAdd(obase + (size_t)q*ODIM, f0);
            atomicAdd(obase + (size_t)(q+1)*ODIM, f1);
        }
    }
}

// ---------------- launch ----------------
extern "C" void kernel_launch(void* const* d_in, const int* in_sizes, int n_in,
                              void* d_out, int out_size) {
    const float* qd = (const float*)d_in[0];
    const float* md = (const float*)d_in[1];
    const int*   mk = (const int*)  d_in[2];
    const float* qw = (const float*)d_in[3];
    const float* kw = (const float*)d_in[4];
    const float* vw = (const float*)d_in[5];
    const float* ow = (const float*)d_in[6];
    const float* ob = (const float*)d_in[7];
    float* out = (float*)d_out;

    cudaFuncSetAttribute(attn_mma_kernel,
                         cudaFuncAttributeMaxDynamicSharedMemorySize, SMEM_SZ);

    proj_kernel    <<<2 + NQBLK + NKBLK, 256>>>(mk, qd, qw, md, kw, vw, ob, out);
    attn_mma_kernel<<<BDIM*H*(NQ/64), 256, SMEM_SZ>>>(ow, out);
}

// round 17
// speedup vs baseline: 1.0848x; 1.0848x over previous
#include <cuda_runtime.h>
#include <cuda_fp16.h>
#include <cstdint>
#include <math.h>

// ---------------- problem constants ----------------
#define BDIM 2
#define NQ   4096
#define NK   4096
#define AQ   128
#define AM   64
#define H    4
#define DK   32
#define DV   16
#define ODIM 64
#define QSCALE (0.17677669529663687f * 1.4426950408889634f)  // scale * log2(e)

// proj grid layout
#define NQBLK (BDIM*NQ/64)     // 128 Q-proj blocks
#define NKBLK (BDIM*NK/32)     // 256 KV-proj blocks

// attn smem stage: K[128][80B] | V[128][48B]; 3 stages
#define OFF_V 10240
#define STG   16384
#define SMEM_SZ (3*STG)

typedef unsigned long long u64;

// ---------------- scratch ----------------
__device__ __align__(16) unsigned short g_Q[(size_t)BDIM*H*NQ*DK]; // fp16, prescaled
__device__ __align__(16) unsigned short g_K[(size_t)BDIM*H*NK*32]; // [bh][pos][32] fp16
__device__ __align__(16) unsigned short g_V[(size_t)BDIM*H*NK*16]; // [bh][pos][16] fp16
__device__ int g_cnt[BDIM];

// ---------------- helpers ----------------
__device__ __forceinline__ uint32_t smem_u32(const void* p) {
    uint32_t a;
    asm("{ .reg .u64 t; cvta.to.shared.u64 t, %1; cvt.u32.u64 %0, t; }" : "=r"(a) : "l"(p));
    return a;
}
__device__ __forceinline__ float ex2f(float x) {
    float y; asm("ex2.approx.f32 %0, %1;" : "=f"(y) : "f"(x)); return y;
}
__device__ __forceinline__ float rcpf(float x) {
    float y; asm("rcp.approx.f32 %0, %1;" : "=f"(y) : "f"(x)); return y;
}
__device__ __forceinline__ uint32_t ex2h2(uint32_t x) {
    uint32_t y; asm("ex2.approx.f16x2 %0, %1;" : "=r"(y) : "r"(x)); return y;
}
__device__ __forceinline__ uint32_t pkf2h(float a, float b) {
    __half2 t = __floats2half2_rn(a, b);
    return *reinterpret_cast<uint32_t*>(&t);
}
__device__ __forceinline__ u64 ffma2(u64 a, u64 b, u64 c) {
    u64 d; asm("fma.rn.f32x2 %0, %1, %2, %3;" : "=l"(d) : "l"(a), "l"(b), "l"(c)); return d;
}
__device__ __forceinline__ u64 pack2(float x, float y) {
    u64 d; asm("mov.b64 %0, {%1,%2};" : "=l"(d) : "f"(x), "f"(y)); return d;
}
__device__ __forceinline__ void unpack2(float& x, float& y, u64 v) {
    asm("mov.b64 {%0,%1}, %2;" : "=f"(x), "=f"(y) : "l"(v));
}
__device__ __forceinline__ unsigned short h16(float x) {
    __half h = __float2half(x);
    return *reinterpret_cast<unsigned short*>(&h);
}
__device__ __forceinline__ void mma16816h(float c[4], const uint32_t a[4], const uint32_t b[2]) {
    asm volatile("mma.sync.aligned.m16n8k16.row.col.f32.f16.f16.f32 "
        "{%0,%1,%2,%3}, {%4,%5,%6,%7}, {%8,%9}, {%0,%1,%2,%3};"
        : "+f"(c[0]), "+f"(c[1]), "+f"(c[2]), "+f"(c[3])
        : "r"(a[0]), "r"(a[1]), "r"(a[2]), "r"(a[3]), "r"(b[0]), "r"(b[1]));
}
__device__ __forceinline__ void ldmx4(uint32_t& v0, uint32_t& v1, uint32_t& v2, uint32_t& v3,
                                      uint32_t addr) {
    asm volatile("ldmatrix.sync.aligned.m8n8.x4.shared.b16 {%0,%1,%2,%3}, [%4];"
        : "=r"(v0), "=r"(v1), "=r"(v2), "=r"(v3) : "r"(addr));
}
__device__ __forceinline__ void ldmx4t(uint32_t& v0, uint32_t& v1, uint32_t& v2, uint32_t& v3,
                                       uint32_t addr) {
    asm volatile("ldmatrix.sync.aligned.m8n8.x4.trans.shared.b16 {%0,%1,%2,%3}, [%4];"
        : "=r"(v0), "=r"(v1), "=r"(v2), "=r"(v3) : "r"(addr));
}
__device__ __forceinline__ void cpa16(uint32_t dst, const void* src) {
    asm volatile("cp.async.cg.shared.global [%0], [%1], 16;" :: "r"(dst), "l"(src));
}
#define CPA_COMMIT() asm volatile("cp.async.commit_group;" ::: "memory")
#define CPA_WAIT(n)  asm volatile("cp.async.wait_group %0;" :: "n"(n) : "memory")

// ================= fused projection kernel (unchanged from R15) =================
__global__ __launch_bounds__(256) void proj_kernel(
    const int* __restrict__ mask,
    const float* __restrict__ qd, const float* __restrict__ qw,
    const float* __restrict__ md, const float* __restrict__ kw,
    const float* __restrict__ vw,
    const float* __restrict__ ob, float* __restrict__ out) {
    __shared__ float rowT[AQ][66];
    __shared__ int wsum[8];
    __shared__ int s_val;
    __shared__ int pos_s[32];
    int t = threadIdx.x;
    int lane = t & 31, wid = t >> 5;

    if (blockIdx.x < 2) {
        int b = blockIdx.x;
        const int4* mb4 = (const int4*)(mask + (size_t)b*NK);
        int c = 0;
        for (int i = t; i < NK/4; i += 256) {
            int4 v = mb4[i];
            c += (v.x != 0) + (v.y != 0) + (v.z != 0) + (v.w != 0);
        }
        #pragma unroll
        for (int d = 16; d > 0; d >>= 1) c += __shfl_xor_sync(0xffffffffu, c, d);
        if (lane == 0) wsum[wid] = c;
        __syncthreads();
        if (t == 0) {
            int s = 0;
            #pragma unroll
            for (int i = 0; i < 8; i++) s += wsum[i];
            g_cnt[b] = s; s_val = s;
        }
        __syncthreads();
        int cnt = s_val;
        int pad = ((cnt + 127) & ~127) - cnt;
        uint4 z = make_uint4(0,0,0,0);
        for (int i = t; i < pad*4*4; i += 256) {
            int h = i / (pad*4), r = i % (pad*4);
            ((uint4*)(g_K + ((size_t)(b*H + h)*NK + cnt + (r >> 2))*32))[r & 3] = z;
        }
        for (int i = t; i < pad*4*2; i += 256) {
            int h = i / (pad*2), r = i % (pad*2);
            ((uint4*)(g_V + ((size_t)(b*H + h)*NK + cnt + (r >> 1))*16))[r & 1] = z;
        }
    } else if (blockIdx.x < 2 + NQBLK) {
        int bq0 = (int)(blockIdx.x - 2)*64;
        int b = bq0 >> 12;
        for (int i = t; i < 64*AQ; i += 256) {
            int r = i >> 7, a = i & 127;
            rowT[a][r] = qd[(size_t)(bq0 + r)*AQ + a];
        }
        __syncthreads();

        int rbase = wid*8;
        int c0 = lane*4;
        u64 acc[4][4];
        #pragma unroll
        for (int ci = 0; ci < 4; ci++)
            #pragma unroll
            for (int rp = 0; rp < 4; rp++) acc[ci][rp] = 0ull;

        for (int a = 0; a < AQ; a++) {
            float4 w4 = *(const float4*)(qw + a*(H*DK) + c0);
            u64 r0 = *(const u64*)&rowT[a][rbase];
            u64 r1 = *(const u64*)&rowT[a][rbase+2];
            u64 r2 = *(const u64*)&rowT[a][rbase+4];
            u64 r3 = *(const u64*)&rowT[a][rbase+6];
            u64 wx = pack2(w4.x, w4.x), wy = pack2(w4.y, w4.y);
            u64 wz = pack2(w4.z, w4.z), ww = pack2(w4.w, w4.w);
            acc[0][0] = ffma2(r0, wx, acc[0][0]); acc[0][1] = ffma2(r1, wx, acc[0][1]);
            acc[0][2] = ffma2(r2, wx, acc[0][2]); acc[0][3] = ffma2(r3, wx, acc[0][3]);
            acc[1][0] = ffma2(r0, wy, acc[1][0]); acc[1][1] = ffma2(r1, wy, acc[1][1]);
            acc[1][2] = ffma2(r2, wy, acc[1][2]); acc[1][3] = ffma2(r3, wy, acc[1][3]);
            acc[2][0] = ffma2(r0, wz, acc[2][0]); acc[2][1] = ffma2(r1, wz, acc[2][1]);
            acc[2][2] = ffma2(r2, wz, acc[2][2]); acc[2][3] = ffma2(r3, wz, acc[2][3]);
            acc[3][0] = ffma2(r0, ww, acc[3][0]); acc[3][1] = ffma2(r1, ww, acc[3][1]);
            acc[3][2] = ffma2(r2, ww, acc[3][2]); acc[3][3] = ffma2(r3, ww, acc[3][3]);
        }

        int h = c0 >> 5, cc = c0 & 31;
        unsigned short* qb = g_Q + ((size_t)(b*H + h)*NQ + (bq0 & (NQ-1))) * DK + cc;
        #pragma unroll
        for (int rp = 0; rp < 4; rp++) {
            float f[4][2];
            #pragma unroll
            for (int ci = 0; ci < 4; ci++) unpack2(f[ci][0], f[ci][1], acc[ci][rp]);
            #pragma unroll
            for (int e = 0; e < 2; e++) {
                int r = rbase + 2*rp + e;
                u64 pk = (u64)h16(f[0][e]*QSCALE)
                       | ((u64)h16(f[1][e]*QSCALE) << 16)
                       | ((u64)h16(f[2][e]*QSCALE) << 32)
                       | ((u64)h16(f[3][e]*QSCALE) << 48);
                *(u64*)(qb + (size_t)r*DK) = pk;
            }
        }
        const float4* b4 = (const float4*)ob;
        for (int i = t; i < 64*16; i += 256) {
            int r = i >> 4, c4 = i & 15;
            ((float4*)(out + (size_t)(bq0 + r)*ODIM))[c4] = b4[c4];
        }
    } else {
        int k0 = (int)(blockIdx.x - 2 - NQBLK)*32;
        int b = k0 >> 12;
        int k0l = k0 & (NK-1);
        const int* mb = mask + (size_t)b*NK;

        int c = 0;
        const int4* mb4 = (const int4*)mb;
        for (int i = t; i < (k0l >> 2); i += 256) {
            int4 v = mb4[i];
            c += (v.x != 0) + (v.y != 0) + (v.z != 0) + (v.w != 0);
        }
        for (int i = t; i < 32*AM; i += 256) {
            int r = i >> 6, a = i & 63;
            rowT[a][r] = md[(size_t)(k0 + r)*AM + a];
        }
        #pragma unroll
        for (int d = 16; d > 0; d >>= 1) c += __shfl_xor_sync(0xffffffffu, c, d);
        if (lane == 0) wsum[wid] = c;
        __syncthreads();
        if (t == 0) {
            int s = 0;
            #pragma unroll
            for (int i = 0; i < 8; i++) s += wsum[i];
            s_val = s;
        }
        __syncthreads();
        if (wid == 0) {
            int m = mb[k0l + lane];
            int incl = (m != 0);
            #pragma unroll
            for (int d = 1; d < 32; d <<= 1) {
                int n = __shfl_up_sync(0xffffffffu, incl, d);
                if (lane >= d) incl += n;
            }
            pos_s[lane] = (m != 0) ? (s_val + incl - 1) : -1;
        }
        __syncthreads();

        if (wid < 4) {
            int rbase = wid*8, c0 = lane*4;
            u64 acc[4][4];
            #pragma unroll
            for (int ci = 0; ci < 4; ci++)
                #pragma unroll
                for (int rp = 0; rp < 4; rp++) acc[ci][rp] = 0ull;
            for (int a = 0; a < AM; a++) {
                float4 w4 = *(const float4*)(kw + a*(H*DK) + c0);
                u64 r0 = *(const u64*)&rowT[a][rbase];
                u64 r1 = *(const u64*)&rowT[a][rbase+2];
                u64 r2 = *(const u64*)&rowT[a][rbase+4];
                u64 r3 = *(const u64*)&rowT[a][rbase+6];
                u64 wx = pack2(w4.x, w4.x), wy = pack2(w4.y, w4.y);
                u64 wz = pack2(w4.z, w4.z), ww = pack2(w4.w, w4.w);
                acc[0][0] = ffma2(r0, wx, acc[0][0]); acc[0][1] = ffma2(r1, wx, acc[0][1]);
                acc[0][2] = ffma2(r2, wx, acc[0][2]); acc[0][3] = ffma2(r3, wx, acc[0][3]);
                acc[1][0] = ffma2(r0, wy, acc[1][0]); acc[1][1] = ffma2(r1, wy, acc[1][1]);
                acc[1][2] = ffma2(r2, wy, acc[1][2]); acc[1][3] = ffma2(r3, wy, acc[1][3]);
                acc[2][0] = ffma2(r0, wz, acc[2][0]); acc[2][1] = ffma2(r1, wz, acc[2][1]);
                acc[2][2] = ffma2(r2, wz, acc[2][2]); acc[2][3] = ffma2(r3, wz, acc[2][3]);
                acc[3][0] = ffma2(r0, ww, acc[3][0]); acc[3][1] = ffma2(r1, ww, acc[3][1]);
                acc[3][2] = ffma2(r2, ww, acc[3][2]); acc[3][3] = ffma2(r3, ww, acc[3][3]);
            }
            int h = c0 >> 5, cc = c0 & 31;
            unsigned short* kb = g_K + (size_t)(b*H + h)*NK*32 + cc;
            #pragma unroll
            for (int rp = 0; rp < 4; rp++) {
                float f[4][2];
                #pragma unroll
                for (int ci = 0; ci < 4; ci++) unpack2(f[ci][0], f[ci][1], acc[ci][rp]);
                #pragma unroll
                for (int e = 0; e < 2; e++) {
                    int pos = pos_s[rbase + 2*rp + e];
                    if (pos < 0) continue;
                    u64 pk = (u64)h16(f[0][e]) | ((u64)h16(f[1][e]) << 16)
                           | ((u64)h16(f[2][e]) << 32) | ((u64)h16(f[3][e]) << 48);
                    *(u64*)(kb + (size_t)pos*32) = pk;
                }
            }
        } else if (wid < 6) {
            int rbase = (wid - 4)*16, c0 = lane*2;
            u64 acc[2][8];
            #pragma unroll
            for (int ci = 0; ci < 2; ci++)
                #pragma unroll
                for (int rp = 0; rp < 8; rp++) acc[ci][rp] = 0ull;
            for (int a = 0; a < AM; a++) {
                float2 w2 = *(const float2*)(vw + a*(H*DV) + c0);
                u64 wx = pack2(w2.x, w2.x), wy = pack2(w2.y, w2.y);
                #pragma unroll
                for (int rp = 0; rp < 8; rp++) {
                    u64 rr = *(const u64*)&rowT[a][rbase + 2*rp];
                    acc[0][rp] = ffma2(rr, wx, acc[0][rp]);
                    acc[1][rp] = ffma2(rr, wy, acc[1][rp]);
                }
            }
            int h = c0 >> 4, cc = c0 & 15;
            unsigned short* vb = g_V + (size_t)(b*H + h)*NK*16 + cc;
            #pragma unroll
            for (int rp = 0; rp < 8; rp++) {
                float f0a, f0b, f1a, f1b;
                unpack2(f0a, f0b, acc[0][rp]);
                unpack2(f1a, f1b, acc[1][rp]);
                int p0 = pos_s[rbase + 2*rp], p1 = pos_s[rbase + 2*rp + 1];
                if (p0 >= 0) {
                    uint32_t pk = (uint32_t)h16(f0a) | ((uint32_t)h16(f1a) << 16);
                    *(uint32_t*)(vb + (size_t)p0*16) = pk;
                }
                if (p1 >= 0) {
                    uint32_t pk = (uint32_t)h16(f0b) | ((uint32_t)h16(f1b) << 16);
                    *(uint32_t*)(vb + (size_t)p1*16) = pk;
                }
            }
        }
    }
}

// ---------------- stage 2: attention, q-tile 128, 8 warps, fused outproj ----------------
// grid = B*H*(NQ/128) = 256 blocks x 256 threads. Warp w owns q-rows [w*16, +16),
// processes ALL 128 keys per tile (two 64-key halves) — R15 warp body verbatim.
__device__ __forceinline__ void issue_tile(const unsigned char* Kg, const unsigned char* Vg,
                                           uint32_t stage, int tid) {
    #pragma unroll
    for (int i = 0; i < 2; i++) {                 // K tile 8KB: 512 x 16B over 256 thr
        int c = tid + (i << 8);
        int row = c >> 2, part = c & 3;
        cpa16(stage + (uint32_t)(row*80 + part*16), Kg + (size_t)c*16);
    }
    {                                             // V tile 4KB: 256 x 16B
        int row = tid >> 1, hf = tid & 1;
        cpa16(stage + OFF_V + (uint32_t)(row*48 + hf*16), Vg + (size_t)tid*16);
    }
}

__global__ __launch_bounds__(256) void attn_mma_kernel(
    const float* __restrict__ ow, float* __restrict__ out) {
    extern __shared__ __align__(16) unsigned char smem[];
    uint32_t sb = smem_u32(smem);
    int tid = threadIdx.x, warp = tid >> 5, lane = tid & 31;
    int g = lane >> 2, tg = lane & 3;
    int bid = blockIdx.x;
    int qt = bid & 31, bh = bid >> 5;            // NQ/128 = 32 q-tiles
    int b = bh >> 2, h = bh & 3;
    int cnt = g_cnt[b];
    int ntiles = (cnt + 127) >> 7;

    uint32_t aQ[2][4];
    {
        const unsigned short* Qb = g_Q + (size_t)bh*NQ*DK;
        int r0 = qt*128 + warp*16 + g;
        #pragma unroll
        for (int s = 0; s < 2; s++)
            #pragma unroll
            for (int p = 0; p < 4; p++) {
                int row = r0 + (p & 1)*8;
                int col = tg*2 + s*16 + (p >> 1)*8;
                aQ[s][p] = *(const uint32_t*)(Qb + (size_t)row*DK + col);
            }
    }

    float o0[4] = {0.f,0.f,0.f,0.f}, o1[4] = {0.f,0.f,0.f,0.f};
    float oL[4] = {0.f,0.f,0.f,0.f};
    const uint32_t ones2 = 0x3C003C00u;
    uint32_t bOnes[2] = {ones2, ones2};

    const unsigned char* Kg = (const unsigned char*)g_K + (size_t)bh*NK*64;
    const unsigned char* Vg = (const unsigned char*)g_V + (size_t)bh*NK*32;

    int sel = lane >> 3;
    uint32_t kbase_lane = (uint32_t)((lane & 7)*80 + sel*16);

    issue_tile(Kg, Vg, sb, tid);
    CPA_COMMIT();

    int cur = 0;
    for (int t = 0; t < ntiles; t++) {
        int nxt = (cur == 2) ? 0 : cur + 1;
        if (t + 1 < ntiles) {
            issue_tile(Kg + (size_t)(t+1)*8192, Vg + (size_t)(t+1)*4096,
                       sb + (uint32_t)nxt*STG, tid);
            CPA_COMMIT();
            CPA_WAIT(1);
        } else {
            CPA_WAIT(0);
        }
        __syncthreads();

        uint32_t sK = sb + (uint32_t)cur*STG;
        uint32_t sV = sK + OFF_V;
        int kb = t << 7;
        bool full = (kb + 128) <= cnt;

        #pragma unroll
        for (int hf = 0; hf < 2; hf++) {
            float sc[8][4];
            #pragma unroll
            for (int j = 0; j < 8; j++)
                sc[j][0] = sc[j][1] = sc[j][2] = sc[j][3] = 0.f;

            uint32_t kaddr = sK + kbase_lane + (uint32_t)(hf*5120);
            #pragma unroll
            for (int j = 0; j < 8; j++) {
                uint32_t v0, v1, v2, v3;
                ldmx4(v0, v1, v2, v3, kaddr);
                kaddr += 640;
                uint32_t k0r[2] = {v0, v1}, k1r[2] = {v2, v3};
                mma16816h(sc[j], aQ[0], k0r);
                mma16816h(sc[j], aQ[1], k1r);
            }

            uint32_t P[8][2];
            if (full) {
                #pragma unroll
                for (int j = 0; j < 8; j++) {
                    P[j][0] = ex2h2(pkf2h(sc[j][0], sc[j][1]));
                    P[j][1] = ex2h2(pkf2h(sc[j][2], sc[j][3]));
                }
            } else {
                int kb2 = kb + hf*64;
                #pragma unroll
                for (int j = 0; j < 8; j++) {
                    float p[4];
                    #pragma unroll
                    for (int e = 0; e < 4; e++) {
                        float pv = ex2f(sc[j][e]);
                        int key = kb2 + j*8 + tg*2 + (e & 1);
                        p[e] = (key < cnt) ? pv : 0.f;
                    }
                    P[j][0] = pkf2h(p[0], p[1]);
                    P[j][1] = pkf2h(p[2], p[3]);
                }
            }

            #pragma unroll
            for (int ks = 0; ks < 4; ks++) {
                uint32_t aP[4] = {P[2*ks][0], P[2*ks][1], P[2*ks+1][0], P[2*ks+1][1]};
                int part = lane >> 3;
                int key = hf*64 + ks*16 + ((part >> 1) << 3) + (lane & 7);
                uint32_t addr = sV + (uint32_t)(key*48 + (part & 1)*16);
                uint32_t v0, v1, v2, v3;
                ldmx4t(v0, v1, v2, v3, addr);
                uint32_t bA[2] = {v0, v2}, bB[2] = {v1, v3};
                mma16816h(o0, aP, bA);
                mma16816h(o1, aP, bB);
                mma16816h(oL, aP, bOnes);
            }
        }
        cur = nxt;
    }

    // ---- fused epilogue: normalize + per-head output projection + RED.ADD ----
    float inv0 = rcpf(oL[0]), inv1 = rcpf(oL[2]);

    __syncthreads();                             // all warps done with stage smem
    float* was = (float*)smem;                   // [16][132] = 8448 B (reuses stages)
    int row0 = warp*16 + g;
    #pragma unroll
    for (int jn = 0; jn < 2; jn++) {
        const float* o = jn ? o1 : o0;
        int chan = jn*8 + tg*2;
        was[(chan+0)*132 + row0]     = o[0]*inv0;
        was[(chan+1)*132 + row0]     = o[1]*inv0;
        was[(chan+0)*132 + row0 + 8] = o[2]*inv1;
        was[(chan+1)*132 + row0 + 8] = o[3]*inv1;
    }
    __syncthreads();

    {
        int oc = tid & 63;
        int grp = tid >> 6;                      // 0..3 -> rows [grp*32, +32)
        float wreg[16];
        #pragma unroll
        for (int i = 0; i < 16; i++)
            wreg[i] = ow[(h*16 + i)*ODIM + oc];
        float* obase = out + ((size_t)b*NQ + qt*128)*ODIM + oc;
        #pragma unroll
        for (int qp = 0; qp < 16; qp++) {
            int q = grp*32 + qp*2;
            u64 acc = 0ull;
            #pragma unroll
            for (int i = 0; i < 16; i++)
                acc = ffma2(*(const u64*)&was[i*132 + q], pack2(wreg[i], wreg[i]), acc);
            float f0, f1; unpack2(f0, f1, acc);
            atomicAdd(obase + (size_t)q*ODIM, f0);
            atomicAdd(obase + (size_t)(q+1)*ODIM, f1);
        }
    }
}

// ---------------- launch ----------------
extern "C" void kernel_launch(void* const* d_in, const int* in_sizes, int n_in,
                              void* d_out, int out_size) {
    const float* qd = (const float*)d_in[0];
    const float* md = (const float*)d_in[1];
    const int*   mk = (const int*)  d_in[2];
    const float* qw = (const float*)d_in[3];
    const float* kw = (const float*)d_in[4];
    const float* vw = (const float*)d_in[5];
    const float* ow = (const float*)d_in[6];
    const float* ob = (const float*)d_in[7];
    float* out = (float*)d_out;

    cudaFuncSetAttribute(attn_mma_kernel,
                         cudaFuncAttributeMaxDynamicSharedMemorySize, SMEM_SZ);

    proj_kernel    <<<2 + NQBLK + NKBLK, 256>>>(mk, qd, qw, md, kw, vw, ob, out);
    attn_mma_kernel<<<BDIM*H*(NQ/128), 256, SMEM_SZ>>>(ow, out);
}